// round 13
// baseline (speedup 1.0000x reference)
#include <cuda_runtime.h>
#include <math.h>

// Problem constants
#define NPARTS   2
#define NFULL    24576
#define M        8192
#define SCALE    (1.0f/8192.0f)

// Single persistent kernel: 288 blocks = 2 parts x 16 i-strips x 9 j-ranges
// 2 blocks/SM resident (enforced by __launch_bounds__(TPB,2) => <=128 regs)
#define NBLK     288
#define TPB      256
#define NWARP    8
#define IPT      16            // warp covers 32*16 = 512 i
#define TI       512
#define NSTRIP   16            // M/TI
#define SLABJ    9             // j-ranges: 2 x 911 + 7 x 910 = 8192
#define JMAX     911

#define INF_BITS 0x7f800000u

// Scratch (__device__ globals; every slot overwritten each run, counters monotonic)
__device__ unsigned int g_rowpart[NPARTS][SLABJ][M];   // per-j-range row-min slices
__device__ unsigned int g_colpart[NPARTS][NSTRIP][M];  // per-i-strip col-min slices
__device__ float        g_sums[4];                     // row p0,p1, col p0,p1
__device__ unsigned int g_bar;    // monotonic grid barrier counter
__device__ unsigned int g_done;   // monotonic completion counter

// ---------------------------------------------------------------------------
__device__ __forceinline__ void make_T(const float* __restrict__ q4,
                                       const float* __restrict__ t3, float* T) {
    float n = sqrtf(q4[0]*q4[0] + q4[1]*q4[1] + q4[2]*q4[2] + q4[3]*q4[3]);
    float a = q4[0]/n, b = q4[1]/n, c = q4[2]/n, d = q4[3]/n;
    T[0] = 1.f - 2.f*c*c - 2.f*d*d; T[1] = 2.f*b*c - 2.f*a*d;       T[2]  = 2.f*a*c + 2.f*b*d;       T[3]  = t3[0];
    T[4] = 2.f*b*c + 2.f*a*d;       T[5] = 1.f - 2.f*b*b - 2.f*d*d; T[6]  = 2.f*c*d - 2.f*a*b;       T[7]  = t3[1];
    T[8] = 2.f*b*d - 2.f*a*c;       T[9] = 2.f*a*b + 2.f*c*d;       T[10] = 1.f - 2.f*b*b - 2.f*c*c; T[11] = t3[2];
}

// ---------------------------------------------------------------------------
__global__ __launch_bounds__(TPB, 2) void k_all(
        const float* __restrict__ cam, const float* __restrict__ cad,
        const float* __restrict__ w,   const float* __restrict__ quat,
        const float* __restrict__ tra, const float* __restrict__ jaxes,
        float* __restrict__ out, int out_size) {
    __shared__ float4 ytile[JMAX];          // 14576 B
    __shared__ unsigned int rowred[TI];     //  2048 B
    __shared__ float sh[NWARP];

    int tid  = threadIdx.x;
    int wix  = tid >> 5;
    int lane = tid & 31;
    int b    = blockIdx.x;
    int part = b / (NSTRIP * SLABJ);        // 0..1
    int r    = b % (NSTRIP * SLABJ);
    int ib   = r / SLABJ;                   // 0..15 (512-i strip)
    int jr   = r % SLABJ;                   // 0..8
    int j0   = jr * 910 + min(jr, 2);
    int jlen = (jr < 2) ? 911 : 910;

    // block 0: zero sums + out tail (ordered before phase C by the barrier)
    if (b == 0) {
        if (tid < 4) g_sums[tid] = 0.0f;
        for (int i = 34 + tid; i < out_size; i += TPB) out[i] = 0.0f;
    }

    // ---- Phase A: self-pack ----
    float T[12];
    make_T(quat + 4 * part, tra + 3 * part, T);

    // X strip (transformed cad) into registers: i = ib*512 + k*32 + lane
    float xr[IPT], yr[IPT], zr[IPT], sr[IPT], row[IPT];
    {
        const float* cbase = cad + (long)part * (NFULL * 3) + (long)(ib * TI + lane) * 9;
        #pragma unroll
        for (int k = 0; k < IPT; k++) {
            const float* cp = cbase + k * (32 * 9);
            float x = cp[0], y = cp[1], z = cp[2];
            float tx = T[0]*x + T[1]*y + T[2]*z  + T[3];
            float ty = T[4]*x + T[5]*y + T[6]*z  + T[7];
            float tz = T[8]*x + T[9]*y + T[10]*z + T[11];
            xr[k] = tx; yr[k] = ty; zr[k] = tz;
            sr[k] = tx*tx + ty*ty + tz*tz;
            row[k] = __int_as_float(INF_BITS);
        }
    }

    // Y range (cam, transform-free) into smem, prescaled by -2
    {
        const float* qbase = cam + (long)part * (NFULL * 3) + (long)j0 * 9;
        for (int t = tid; t < jlen; t += TPB) {
            const float* qp = qbase + t * 9;
            float cx = qp[0], cy = qp[1], cz = qp[2];
            ytile[t] = make_float4(-2.f*cx, -2.f*cy, -2.f*cz, cx*cx + cy*cy + cz*cz);
        }
    }
    #pragma unroll
    for (int s2 = 0; s2 < TI / TPB; s2++) rowred[tid + s2 * TPB] = INF_BITS;
    __syncthreads();     // the ONE sync before the hot loop

    // ---- Phase B: chamfer sweep (per warp: j = wix, wix+8, ...) ----
    #pragma unroll 2
    for (int jl = wix; jl < jlen; jl += NWARP) {
        float4 y4 = ytile[jl];            // LDS.128 broadcast, conflict-free
        float col = __int_as_float(INF_BITS);
        #pragma unroll
        for (int k = 0; k < IPT; k++) {
            float s = fmaf(y4.x, xr[k],
                      fmaf(y4.y, yr[k],
                      fmaf(y4.z, zr[k], sr[k])));   // -2 x.y + |x|^2
            row[k] = fminf(row[k], s + y4.w);        // full d2
            col    = fminf(col, s);
        }
        #pragma unroll
        for (int o = 16; o > 0; o >>= 1)
            col = fminf(col, __shfl_xor_sync(0xffffffffu, col, o));
        if (lane == 0) {
            float v = fmaxf(col + y4.w, 0.0f);
            g_colpart[part][ib][j0 + jl] = __float_as_uint(v);   // plain STG
        }
    }

    // merge row partials across warps, store slice (plain STG, full coverage)
    #pragma unroll
    for (int k = 0; k < IPT; k++) {
        float v = fmaxf(row[k], 0.0f);
        atomicMin(&rowred[k * 32 + lane], __float_as_uint(v));
    }
    __syncthreads();
    #pragma unroll
    for (int s2 = 0; s2 < TI / TPB; s2++) {
        int il = tid + s2 * TPB;
        g_rowpart[part][jr][ib * TI + il] = rowred[il];
    }

    // ---- grid barrier (monotonic: replay-safe, no reset kernel) ----
    __threadfence();
    __syncthreads();
    if (tid == 0) {
        unsigned int old = atomicAdd(&g_bar, 1u);
        unsigned int target = (old / NBLK + 1u) * NBLK;
        while (*(volatile unsigned int*)&g_bar < target) __nanosleep(64);
    }
    __syncthreads();
    __threadfence();

    // ---- Phase C: reduce mins -> sums ----
    int gidx = b * TPB + tid;       // blocks 0..127 cover the 32768 entries
    float val = 0.0f;
    if (gidx < 2 * NPARTS * M) {
        unsigned int mb = INF_BITS;
        if (gidx < NPARTS * M) {
            int p = gidx >> 13, i = gidx & (M - 1);
            #pragma unroll
            for (int s = 0; s < SLABJ; s++)
                mb = min(mb, __ldcg(&g_rowpart[p][s][i]));
        } else {
            int g2 = gidx - NPARTS * M;
            int p = g2 >> 13, j = g2 & (M - 1);
            #pragma unroll
            for (int s = 0; s < NSTRIP; s++)
                mb = min(mb, __ldcg(&g_colpart[p][s][j]));
        }
        val = sqrtf(__uint_as_float(mb));
        #pragma unroll
        for (int o = 16; o > 0; o >>= 1)
            val += __shfl_xor_sync(0xffffffffu, val, o);
        if (lane == 0) sh[wix] = val;
    }
    __syncthreads();
    if (tid == 0) {
        if (gidx < 2 * NPARTS * M) {      // sidx uniform per block
            float s = 0.f;
            #pragma unroll
            for (int k2 = 0; k2 < NWARP; k2++) s += sh[k2];
            atomicAdd(&g_sums[gidx >> 13], s);
        }
        __threadfence();
        unsigned int old = atomicAdd(&g_done, 1u);
        if (old % NBLK == NBLK - 1) {     // last block out: finalize
            __threadfence();
            float TT[2][12];
            for (int pp = 0; pp < 2; pp++) {
                make_T(quat + 4*pp, tra + 3*pp, TT[pp]);
                for (int rr = 0; rr < 3; rr++)
                    for (int c = 0; c < 4; c++)
                        out[2 + pp*16 + rr*4 + c] = TT[pp][rr*4 + c];
                out[2 + pp*16 + 12] = 0.f; out[2 + pp*16 + 13] = 0.f;
                out[2 + pp*16 + 14] = 0.f; out[2 + pp*16 + 15] = 1.f;
            }
            float ss = 0.f;
            for (int c2 = 0; c2 < 2; c2++) {
                for (int rr = 0; rr < 3; rr++) {
                    float v0 = 0.f, v1 = 0.f;
                    for (int k2 = 0; k2 < 4; k2++) {
                        v0 += TT[0][rr*4+k2] * jaxes[0*8 + c2*4 + k2];
                        v1 += TT[1][rr*4+k2] * jaxes[1*8 + c2*4 + k2];
                    }
                    float dd = v0 - v1;
                    ss += dd * dd;
                }
                float d3 = jaxes[0*8 + c2*4 + 3] - jaxes[1*8 + c2*4 + 3];
                ss += d3 * d3;            // row 3 of the 4x4 transforms
            }
            float ek = 1.f / (1.f + expf(5.f * sqrtf(ss)));
            out[1] = ek;
            volatile float* vs = g_sums;
            float eg = 0.f;
            for (int pp = 0; pp < 2; pp++)
                eg += w[pp] * ((vs[pp] + vs[2 + pp]) * SCALE);
            out[0] = eg + w[NPARTS] * ek;
        }
    }
}

// ---------------------------------------------------------------------------
extern "C" void kernel_launch(void* const* d_in, const int* in_sizes, int n_in,
                              void* d_out, int out_size) {
    const float* cam  = (const float*)d_in[0];
    const float* cad  = (const float*)d_in[1];
    const float* w    = (const float*)d_in[2];
    const float* quat = (const float*)d_in[3];
    const float* tra  = (const float*)d_in[4];
    const float* jax_ = (const float*)d_in[5];
    float* out = (float*)d_out;

    k_all<<<NBLK, TPB>>>(cam, cad, w, quat, tra, jax_, out, out_size);
}